// round 3
// baseline (speedup 1.0000x reference)
#include <cuda_runtime.h>
#include <cstdint>
#include <math.h>

// Problem constants (fixed shapes from reference)
#define BSZ 16384   // batch
#define FF  2048    // n_features
#define HH  4096    // n_hidden
#define DD  4096    // num_of_demos
#define KK  2048    // num_of_features (loss K)

// Scratch activations (no cudaMalloc allowed)
static __device__ float g_buf0[(size_t)BSZ * HH];
static __device__ float g_buf1[(size_t)BSZ * HH];
static __device__ float g_partial[DD];

// ---------------------------------------------------------------------------
// helpers
// ---------------------------------------------------------------------------
__device__ __forceinline__ uint32_t f2tf(float x) {
    uint32_t r;
    asm("cvt.rna.tf32.f32 %0, %1;" : "=r"(r) : "f"(x));
    return r;
}

__device__ __forceinline__ void mma8(float c[4], const uint32_t a[4], const uint32_t b[2]) {
    asm volatile(
        "mma.sync.aligned.m16n8k8.row.col.f32.tf32.tf32.f32 "
        "{%0,%1,%2,%3}, {%4,%5,%6,%7}, {%8,%9}, {%0,%1,%2,%3};\n"
        : "+f"(c[0]), "+f"(c[1]), "+f"(c[2]), "+f"(c[3])
        : "r"(a[0]), "r"(a[1]), "r"(a[2]), "r"(a[3]), "r"(b[0]), "r"(b[1]));
}

__device__ __forceinline__ void cvt_store4(uint32_t* dst, float4 v) {
    uint4 t;
    t.x = f2tf(v.x); t.y = f2tf(v.y); t.z = f2tf(v.z); t.w = f2tf(v.w);
    *reinterpret_cast<uint4*>(dst) = t;
}

__device__ __forceinline__ float block_sum(float v) {
    #pragma unroll
    for (int o = 16; o; o >>= 1) v += __shfl_xor_sync(0xffffffffu, v, o);
    __shared__ float sh[32];
    const int w = threadIdx.x >> 5;
    if ((threadIdx.x & 31) == 0) sh[w] = v;
    __syncthreads();
    const int nw = (blockDim.x + 31) >> 5;
    v = (threadIdx.x < (unsigned)nw) ? sh[threadIdx.x] : 0.f;
    if (threadIdx.x < 32) {
        #pragma unroll
        for (int o = 16; o; o >>= 1) v += __shfl_xor_sync(0xffffffffu, v, o);
    }
    __syncthreads();
    return v;  // valid in thread 0
}

// ---------------------------------------------------------------------------
// Loss: sum over [D, K] of max(alpha_k*(sl - dm) + 1, 0) - c
// Two-pass deterministic reduction (block per demo row, then single block).
// ---------------------------------------------------------------------------
__global__ void loss_partial_kernel(const float* __restrict__ dm,
                                    const float* __restrict__ alpha,
                                    const float* __restrict__ sl,
                                    const float* __restrict__ cptr) {
    const int j = blockIdx.x;
    const size_t base = (size_t)j * KK;
    const float c = cptr[0];
    float s = 0.f;
    for (int k = threadIdx.x; k < KK; k += blockDim.x) {
        float m = fmaf(alpha[k], sl[base + k] - dm[base + k], 1.0f);
        s += fmaxf(m, 0.f) - c;
    }
    float tot = block_sum(s);
    if (threadIdx.x == 0) g_partial[j] = tot;
}

__global__ void loss_final_kernel(float* __restrict__ lossp) {
    float s = 0.f;
    for (int i = threadIdx.x; i < DD; i += blockDim.x) s += g_partial[i];
    float tot = block_sum(s);
    if (threadIdx.x == 0) lossp[0] = tot;
}

// ---------------------------------------------------------------------------
// GEMM + bias + ReLU.  C[M,N] = relu(A[M,K] @ W[K,N] + bias)
// Tile 128x128x16, 256 threads (8 warps, 4x2), warp tile 32x64,
// tf32 mma.sync m16n8k8, fp32 accumulate. Double-buffered smem.
// Conflict-free pads: APAD=20, BPAD=136.
// ---------------------------------------------------------------------------
#define APAD 20
#define BPAD 136

__global__ __launch_bounds__(256)
void gemm_bias_relu(const float* __restrict__ A, const float* __restrict__ W,
                    const float* __restrict__ bias, float* __restrict__ C,
                    int K, int N) {
    __shared__ __align__(16) uint32_t As[2][128 * APAD];
    __shared__ __align__(16) uint32_t Bs[2][16 * BPAD];

    const int tid = threadIdx.x;
    const int bm = blockIdx.y, bn = blockIdx.x;
    const int wid = tid >> 5, lane = tid & 31;
    const int wm = wid & 3, wn = wid >> 2;          // 4 warps along M, 2 along N
    const int gID = lane >> 2, tig = lane & 3;

    // global->smem tile mapping (each thread: 2 float4 of A, 2 float4 of B)
    const int ar0 = tid >> 2,        ac0 = (tid & 3) * 4;
    const int ar1 = ar0 + 64;
    const int br0 = tid >> 5,        bc0 = (tid & 31) * 4;
    const int br1 = br0 + 8;

    const float* Abase = A + (size_t)bm * 128 * K;
    const float* Wbase = W + (size_t)bn * 128;

    float4 sa0, sa1, sb0, sb1;
    sa0 = *(const float4*)(Abase + (size_t)ar0 * K + ac0);
    sa1 = *(const float4*)(Abase + (size_t)ar1 * K + ac0);
    sb0 = *(const float4*)(Wbase + (size_t)br0 * N + bc0);
    sb1 = *(const float4*)(Wbase + (size_t)br1 * N + bc0);

    cvt_store4(&As[0][ar0 * APAD + ac0], sa0);
    cvt_store4(&As[0][ar1 * APAD + ac0], sa1);
    cvt_store4(&Bs[0][br0 * BPAD + bc0], sb0);
    cvt_store4(&Bs[0][br1 * BPAD + bc0], sb1);
    __syncthreads();

    float acc[2][8][4];
    #pragma unroll
    for (int mt = 0; mt < 2; ++mt)
        #pragma unroll
        for (int nt = 0; nt < 8; ++nt)
            #pragma unroll
            for (int r = 0; r < 4; ++r) acc[mt][nt][r] = 0.f;

    const int KT = K >> 4;
    #pragma unroll 1
    for (int kt = 0; kt < KT; ++kt) {
        const int buf = kt & 1;
        if (kt + 1 < KT) {
            const int k0 = (kt + 1) << 4;
            sa0 = *(const float4*)(Abase + (size_t)ar0 * K + k0 + ac0);
            sa1 = *(const float4*)(Abase + (size_t)ar1 * K + k0 + ac0);
            sb0 = *(const float4*)(Wbase + (size_t)(k0 + br0) * N + bc0);
            sb1 = *(const float4*)(Wbase + (size_t)(k0 + br1) * N + bc0);
        }
        #pragma unroll
        for (int kk = 0; kk < 16; kk += 8) {
            uint32_t a[2][4], b[8][2];
            #pragma unroll
            for (int mt = 0; mt < 2; ++mt) {
                const int m = wm * 32 + mt * 16;
                a[mt][0] = As[buf][(m + gID) * APAD + kk + tig];
                a[mt][1] = As[buf][(m + gID + 8) * APAD + kk + tig];
                a[mt][2] = As[buf][(m + gID) * APAD + kk + tig + 4];
                a[mt][3] = As[buf][(m + gID + 8) * APAD + kk + tig + 4];
            }
            #pragma unroll
            for (int nt = 0; nt < 8; ++nt) {
                const int n = wn * 64 + nt * 8 + gID;
                b[nt][0] = Bs[buf][(kk + tig) * BPAD + n];
                b[nt][1] = Bs[buf][(kk + tig + 4) * BPAD + n];
            }
            #pragma unroll
            for (int mt = 0; mt < 2; ++mt)
                #pragma unroll
                for (int nt = 0; nt < 8; ++nt)
                    mma8(acc[mt][nt], a[mt], b[nt]);
        }
        if (kt + 1 < KT) {
            const int nb = buf ^ 1;
            cvt_store4(&As[nb][ar0 * APAD + ac0], sa0);
            cvt_store4(&As[nb][ar1 * APAD + ac0], sa1);
            cvt_store4(&Bs[nb][br0 * BPAD + bc0], sb0);
            cvt_store4(&Bs[nb][br1 * BPAD + bc0], sb1);
            __syncthreads();
        }
    }

    // Epilogue: bias + relu, float2 stores
    #pragma unroll
    for (int mt = 0; mt < 2; ++mt) {
        const int m0 = bm * 128 + wm * 32 + mt * 16 + gID;
        #pragma unroll
        for (int nt = 0; nt < 8; ++nt) {
            const int n = bn * 128 + wn * 64 + nt * 8 + tig * 2;
            const float bx = bias[n], by = bias[n + 1];
            float2 v0, v1;
            v0.x = fmaxf(acc[mt][nt][0] + bx, 0.f);
            v0.y = fmaxf(acc[mt][nt][1] + by, 0.f);
            v1.x = fmaxf(acc[mt][nt][2] + bx, 0.f);
            v1.y = fmaxf(acc[mt][nt][3] + by, 0.f);
            *(float2*)&C[(size_t)m0 * N + n]       = v0;
            *(float2*)&C[(size_t)(m0 + 8) * N + n] = v1;
        }
    }
}

// ---------------------------------------------------------------------------
// Final layer: probs = sigmoid(h3 @ W4 + b4), W4 is [H, 2] row-major.
// One block (256 threads) per batch row. HBM-bound on h3.
// ---------------------------------------------------------------------------
__global__ void layer4_kernel(const float* __restrict__ h, const float* __restrict__ w4,
                              const float* __restrict__ b4, float* __restrict__ probs) {
    const int row = blockIdx.x;
    const float* hr = h + (size_t)row * HH;
    float s0 = 0.f, s1 = 0.f;
    for (int k = threadIdx.x; k < HH; k += blockDim.x) {
        const float v = hr[k];
        const float2 w = *(const float2*)(w4 + 2 * k);
        s0 = fmaf(v, w.x, s0);
        s1 = fmaf(v, w.y, s1);
    }
    #pragma unroll
    for (int o = 16; o; o >>= 1) {
        s0 += __shfl_xor_sync(0xffffffffu, s0, o);
        s1 += __shfl_xor_sync(0xffffffffu, s1, o);
    }
    __shared__ float sh0[8], sh1[8];
    const int w = threadIdx.x >> 5;
    if ((threadIdx.x & 31) == 0) { sh0[w] = s0; sh1[w] = s1; }
    __syncthreads();
    if (threadIdx.x == 0) {
        float t0 = 0.f, t1 = 0.f;
        #pragma unroll
        for (int i = 0; i < 8; ++i) { t0 += sh0[i]; t1 += sh1[i]; }
        t0 += b4[0]; t1 += b4[1];
        probs[2 * row]     = 1.f / (1.f + expf(-t0));
        probs[2 * row + 1] = 1.f / (1.f + expf(-t1));
    }
}

// ---------------------------------------------------------------------------
// Launch
// ---------------------------------------------------------------------------
extern "C" void kernel_launch(void* const* d_in, const int* in_sizes, int n_in,
                              void* d_out, int out_size) {
    // metadata order: x, demo_metric, alpha, sample_loss, subdom_constant,
    //                 num_of_demos, num_of_features, W1, b1, W2, b2, W3, b3, W4, b4
    // If the two int scalars are not materialized as inputs, shift by -2.
    const int s = (n_in >= 15) ? 0 : -2;
    const float* x     = (const float*)d_in[0];
    const float* dm    = (const float*)d_in[1];
    const float* alpha = (const float*)d_in[2];
    const float* sl    = (const float*)d_in[3];
    const float* cst   = (const float*)d_in[4];
    const float* W1 = (const float*)d_in[7 + s];
    const float* b1 = (const float*)d_in[8 + s];
    const float* W2 = (const float*)d_in[9 + s];
    const float* b2 = (const float*)d_in[10 + s];
    const float* W3 = (const float*)d_in[11 + s];
    const float* b3 = (const float*)d_in[12 + s];
    const float* W4 = (const float*)d_in[13 + s];
    const float* b4 = (const float*)d_in[14 + s];

    float* out = (float*)d_out;
    // tuple (loss, probs): loss scalar first, probs [B,2] after.
    float* probs = out + (out_size - 2 * BSZ);
    float* lossp = (out_size > 2 * BSZ) ? out : nullptr;

    float *buf0 = nullptr, *buf1 = nullptr;
    cudaGetSymbolAddress((void**)&buf0, g_buf0);
    cudaGetSymbolAddress((void**)&buf1, g_buf1);

    // Loss (deterministic two-pass)
    loss_partial_kernel<<<DD, 256>>>(dm, alpha, sl, cst);
    if (lossp) loss_final_kernel<<<1, 1024>>>(lossp);

    // MLP
    dim3 grid(HH / 128, BSZ / 128);  // (N tiles, M tiles)
    gemm_bias_relu<<<grid, 256>>>(x,    W1, b1, buf0, FF, HH);
    gemm_bias_relu<<<grid, 256>>>(buf0, W2, b2, buf1, HH, HH);
    gemm_bias_relu<<<grid, 256>>>(buf1, W3, b3, buf0, HH, HH);
    layer4_kernel<<<BSZ, 256>>>(buf0, W4, b4, probs);
}

// round 4
// speedup vs baseline: 1.0006x; 1.0006x over previous
#include <cuda_runtime.h>
#include <cstdint>
#include <math.h>

// Problem constants (fixed shapes from reference)
#define BSZ 16384   // batch
#define FF  2048    // n_features
#define HH  4096    // n_hidden
#define DD  4096    // num_of_demos
#define KK  2048    // num_of_features (loss K)

// Scratch activations (no cudaMalloc allowed)
static __device__ float g_buf0[(size_t)BSZ * HH];
static __device__ float g_buf1[(size_t)BSZ * HH];
static __device__ float g_partial[DD];

// ---------------------------------------------------------------------------
// helpers
// ---------------------------------------------------------------------------
__device__ __forceinline__ uint32_t f2tf(float x) {
    uint32_t r;
    asm("cvt.rna.tf32.f32 %0, %1;" : "=r"(r) : "f"(x));
    return r;
}

__device__ __forceinline__ void mma8(float c[4], const uint32_t a[4], const uint32_t b[2]) {
    asm volatile(
        "mma.sync.aligned.m16n8k8.row.col.f32.tf32.tf32.f32 "
        "{%0,%1,%2,%3}, {%4,%5,%6,%7}, {%8,%9}, {%0,%1,%2,%3};\n"
        : "+f"(c[0]), "+f"(c[1]), "+f"(c[2]), "+f"(c[3])
        : "r"(a[0]), "r"(a[1]), "r"(a[2]), "r"(a[3]), "r"(b[0]), "r"(b[1]));
}

__device__ __forceinline__ void cvt_store4(uint32_t* dst, float4 v) {
    uint4 t;
    t.x = f2tf(v.x); t.y = f2tf(v.y); t.z = f2tf(v.z); t.w = f2tf(v.w);
    *reinterpret_cast<uint4*>(dst) = t;
}

__device__ __forceinline__ float block_sum(float v) {
    #pragma unroll
    for (int o = 16; o; o >>= 1) v += __shfl_xor_sync(0xffffffffu, v, o);
    __shared__ float sh[32];
    const int w = threadIdx.x >> 5;
    if ((threadIdx.x & 31) == 0) sh[w] = v;
    __syncthreads();
    const int nw = (blockDim.x + 31) >> 5;
    v = (threadIdx.x < (unsigned)nw) ? sh[threadIdx.x] : 0.f;
    if (threadIdx.x < 32) {
        #pragma unroll
        for (int o = 16; o; o >>= 1) v += __shfl_xor_sync(0xffffffffu, v, o);
    }
    __syncthreads();
    return v;  // valid in thread 0
}

// ---------------------------------------------------------------------------
// Loss: sum over [D, K] of max(alpha_k*(sl - dm) + 1, 0) - c
// Two-pass deterministic reduction (block per demo row, then single block).
// ---------------------------------------------------------------------------
__global__ void loss_partial_kernel(const float* __restrict__ dm,
                                    const float* __restrict__ alpha,
                                    const float* __restrict__ sl,
                                    const float* __restrict__ cptr) {
    const int j = blockIdx.x;
    const size_t base = (size_t)j * KK;
    const float c = cptr[0];
    float s = 0.f;
    for (int k = threadIdx.x; k < KK; k += blockDim.x) {
        float m = fmaf(alpha[k], sl[base + k] - dm[base + k], 1.0f);
        s += fmaxf(m, 0.f) - c;
    }
    float tot = block_sum(s);
    if (threadIdx.x == 0) g_partial[j] = tot;
}

__global__ void loss_final_kernel(float* __restrict__ lossp) {
    float s = 0.f;
    for (int i = threadIdx.x; i < DD; i += blockDim.x) s += g_partial[i];
    float tot = block_sum(s);
    if (threadIdx.x == 0) lossp[0] = tot;
}

// ---------------------------------------------------------------------------
// GEMM + bias + ReLU.  C[M,N] = relu(A[M,K] @ W[K,N] + bias)
// Tile 128x128x16, 256 threads (8 warps, 4x2), warp tile 32x64,
// tf32 mma.sync m16n8k8, fp32 accumulate. Double-buffered smem.
// Conflict-free pads: APAD=20, BPAD=136.
// ---------------------------------------------------------------------------
#define APAD 20
#define BPAD 136

__global__ __launch_bounds__(256)
void gemm_bias_relu(const float* __restrict__ A, const float* __restrict__ W,
                    const float* __restrict__ bias, float* __restrict__ C,
                    int K, int N) {
    __shared__ __align__(16) uint32_t As[2][128 * APAD];
    __shared__ __align__(16) uint32_t Bs[2][16 * BPAD];

    const int tid = threadIdx.x;
    const int bm = blockIdx.y, bn = blockIdx.x;
    const int wid = tid >> 5, lane = tid & 31;
    const int wm = wid & 3, wn = wid >> 2;          // 4 warps along M, 2 along N
    const int gID = lane >> 2, tig = lane & 3;

    // global->smem tile mapping (each thread: 2 float4 of A, 2 float4 of B)
    const int ar0 = tid >> 2,        ac0 = (tid & 3) * 4;
    const int ar1 = ar0 + 64;
    const int br0 = tid >> 5,        bc0 = (tid & 31) * 4;
    const int br1 = br0 + 8;

    const float* Abase = A + (size_t)bm * 128 * K;
    const float* Wbase = W + (size_t)bn * 128;

    float4 sa0, sa1, sb0, sb1;
    sa0 = *(const float4*)(Abase + (size_t)ar0 * K + ac0);
    sa1 = *(const float4*)(Abase + (size_t)ar1 * K + ac0);
    sb0 = *(const float4*)(Wbase + (size_t)br0 * N + bc0);
    sb1 = *(const float4*)(Wbase + (size_t)br1 * N + bc0);

    cvt_store4(&As[0][ar0 * APAD + ac0], sa0);
    cvt_store4(&As[0][ar1 * APAD + ac0], sa1);
    cvt_store4(&Bs[0][br0 * BPAD + bc0], sb0);
    cvt_store4(&Bs[0][br1 * BPAD + bc0], sb1);
    __syncthreads();

    float acc[2][8][4];
    #pragma unroll
    for (int mt = 0; mt < 2; ++mt)
        #pragma unroll
        for (int nt = 0; nt < 8; ++nt)
            #pragma unroll
            for (int r = 0; r < 4; ++r) acc[mt][nt][r] = 0.f;

    const int KT = K >> 4;
    #pragma unroll 1
    for (int kt = 0; kt < KT; ++kt) {
        const int buf = kt & 1;
        if (kt + 1 < KT) {
            const int k0 = (kt + 1) << 4;
            sa0 = *(const float4*)(Abase + (size_t)ar0 * K + k0 + ac0);
            sa1 = *(const float4*)(Abase + (size_t)ar1 * K + k0 + ac0);
            sb0 = *(const float4*)(Wbase + (size_t)(k0 + br0) * N + bc0);
            sb1 = *(const float4*)(Wbase + (size_t)(k0 + br1) * N + bc0);
        }
        #pragma unroll
        for (int kk = 0; kk < 16; kk += 8) {
            uint32_t a[2][4], b[8][2];
            #pragma unroll
            for (int mt = 0; mt < 2; ++mt) {
                const int m = wm * 32 + mt * 16;
                a[mt][0] = As[buf][(m + gID) * APAD + kk + tig];
                a[mt][1] = As[buf][(m + gID + 8) * APAD + kk + tig];
                a[mt][2] = As[buf][(m + gID) * APAD + kk + tig + 4];
                a[mt][3] = As[buf][(m + gID + 8) * APAD + kk + tig + 4];
            }
            #pragma unroll
            for (int nt = 0; nt < 8; ++nt) {
                const int n = wn * 64 + nt * 8 + gID;
                b[nt][0] = Bs[buf][(kk + tig) * BPAD + n];
                b[nt][1] = Bs[buf][(kk + tig + 4) * BPAD + n];
            }
            #pragma unroll
            for (int mt = 0; mt < 2; ++mt)
                #pragma unroll
                for (int nt = 0; nt < 8; ++nt)
                    mma8(acc[mt][nt], a[mt], b[nt]);
        }
        if (kt + 1 < KT) {
            const int nb = buf ^ 1;
            cvt_store4(&As[nb][ar0 * APAD + ac0], sa0);
            cvt_store4(&As[nb][ar1 * APAD + ac0], sa1);
            cvt_store4(&Bs[nb][br0 * BPAD + bc0], sb0);
            cvt_store4(&Bs[nb][br1 * BPAD + bc0], sb1);
            __syncthreads();
        }
    }

    // Epilogue: bias + relu, float2 stores
    #pragma unroll
    for (int mt = 0; mt < 2; ++mt) {
        const int m0 = bm * 128 + wm * 32 + mt * 16 + gID;
        #pragma unroll
        for (int nt = 0; nt < 8; ++nt) {
            const int n = bn * 128 + wn * 64 + nt * 8 + tig * 2;
            const float bx = bias[n], by = bias[n + 1];
            float2 v0, v1;
            v0.x = fmaxf(acc[mt][nt][0] + bx, 0.f);
            v0.y = fmaxf(acc[mt][nt][1] + by, 0.f);
            v1.x = fmaxf(acc[mt][nt][2] + bx, 0.f);
            v1.y = fmaxf(acc[mt][nt][3] + by, 0.f);
            *(float2*)&C[(size_t)m0 * N + n]       = v0;
            *(float2*)&C[(size_t)(m0 + 8) * N + n] = v1;
        }
    }
}

// ---------------------------------------------------------------------------
// Final layer: probs = sigmoid(h3 @ W4 + b4), W4 is [H, 2] row-major.
// One block (256 threads) per batch row. HBM-bound on h3.
// ---------------------------------------------------------------------------
__global__ void layer4_kernel(const float* __restrict__ h, const float* __restrict__ w4,
                              const float* __restrict__ b4, float* __restrict__ probs) {
    const int row = blockIdx.x;
    const float* hr = h + (size_t)row * HH;
    float s0 = 0.f, s1 = 0.f;
    for (int k = threadIdx.x; k < HH; k += blockDim.x) {
        const float v = hr[k];
        const float2 w = *(const float2*)(w4 + 2 * k);
        s0 = fmaf(v, w.x, s0);
        s1 = fmaf(v, w.y, s1);
    }
    #pragma unroll
    for (int o = 16; o; o >>= 1) {
        s0 += __shfl_xor_sync(0xffffffffu, s0, o);
        s1 += __shfl_xor_sync(0xffffffffu, s1, o);
    }
    __shared__ float sh0[8], sh1[8];
    const int w = threadIdx.x >> 5;
    if ((threadIdx.x & 31) == 0) { sh0[w] = s0; sh1[w] = s1; }
    __syncthreads();
    if (threadIdx.x == 0) {
        float t0 = 0.f, t1 = 0.f;
        #pragma unroll
        for (int i = 0; i < 8; ++i) { t0 += sh0[i]; t1 += sh1[i]; }
        t0 += b4[0]; t1 += b4[1];
        probs[2 * row]     = 1.f / (1.f + expf(-t0));
        probs[2 * row + 1] = 1.f / (1.f + expf(-t1));
    }
}

// ---------------------------------------------------------------------------
// Launch
// ---------------------------------------------------------------------------
extern "C" void kernel_launch(void* const* d_in, const int* in_sizes, int n_in,
                              void* d_out, int out_size) {
    // metadata order: x, demo_metric, alpha, sample_loss, subdom_constant,
    //                 num_of_demos, num_of_features, W1, b1, W2, b2, W3, b3, W4, b4
    // If the two int scalars are not materialized as inputs, shift by -2.
    const int s = (n_in >= 15) ? 0 : -2;
    const float* x     = (const float*)d_in[0];
    const float* dm    = (const float*)d_in[1];
    const float* alpha = (const float*)d_in[2];
    const float* sl    = (const float*)d_in[3];
    const float* cst   = (const float*)d_in[4];
    const float* W1 = (const float*)d_in[7 + s];
    const float* b1 = (const float*)d_in[8 + s];
    const float* W2 = (const float*)d_in[9 + s];
    const float* b2 = (const float*)d_in[10 + s];
    const float* W3 = (const float*)d_in[11 + s];
    const float* b3 = (const float*)d_in[12 + s];
    const float* W4 = (const float*)d_in[13 + s];
    const float* b4 = (const float*)d_in[14 + s];

    float* out = (float*)d_out;
    // tuple (loss, probs): loss scalar first, probs [B,2] after.
    float* probs = out + (out_size - 2 * BSZ);
    float* lossp = (out_size > 2 * BSZ) ? out : nullptr;

    float *buf0 = nullptr, *buf1 = nullptr;
    cudaGetSymbolAddress((void**)&buf0, g_buf0);
    cudaGetSymbolAddress((void**)&buf1, g_buf1);

    // Loss (deterministic two-pass)
    loss_partial_kernel<<<DD, 256>>>(dm, alpha, sl, cst);
    if (lossp) loss_final_kernel<<<1, 1024>>>(lossp);

    // MLP
    dim3 grid(HH / 128, BSZ / 128);  // (N tiles, M tiles)
    gemm_bias_relu<<<grid, 256>>>(x,    W1, b1, buf0, FF, HH);
    gemm_bias_relu<<<grid, 256>>>(buf0, W2, b2, buf1, HH, HH);
    gemm_bias_relu<<<grid, 256>>>(buf1, W3, b3, buf0, HH, HH);
    layer4_kernel<<<BSZ, 256>>>(buf0, W4, b4, probs);
}

// round 6
// speedup vs baseline: 1.1497x; 1.1490x over previous
#include <cuda_runtime.h>
#include <cstdint>
#include <math.h>

// Problem constants (fixed shapes from reference)
#define BSZ 16384   // batch
#define FF  2048    // n_features
#define HH  4096    // n_hidden
#define DD  4096    // num_of_demos
#define KK  2048    // num_of_features (loss K)

// Scratch (no cudaMalloc allowed)
static __device__ float g_buf0[(size_t)BSZ * HH];
static __device__ float g_buf1[(size_t)BSZ * HH];
static __device__ float g_xr  [(size_t)BSZ * FF];
static __device__ float g_w1r [(size_t)FF  * HH];
static __device__ float g_w2r [(size_t)HH  * HH];
static __device__ float g_w3r [(size_t)HH  * HH];
static __device__ float g_partial[DD];

// ---------------------------------------------------------------------------
// helpers
// ---------------------------------------------------------------------------
__device__ __forceinline__ uint32_t f2tf(float x) {
    uint32_t r;
    asm("cvt.rna.tf32.f32 %0, %1;" : "=r"(r) : "f"(x));
    return r;
}
__device__ __forceinline__ float rna_f(float x) { return __uint_as_float(f2tf(x)); }

__device__ __forceinline__ uint32_t smem_u32(const void* p) {
    uint32_t a;
    asm("{ .reg .u64 t; cvta.to.shared.u64 t, %1; cvt.u32.u64 %0, t; }" : "=r"(a) : "l"(p));
    return a;
}
__device__ __forceinline__ void cp_async16(uint32_t dst, const void* src) {
    asm volatile("cp.async.cg.shared.global [%0], [%1], 16;" :: "r"(dst), "l"(src) : "memory");
}
__device__ __forceinline__ uint32_t lds32(uint32_t addr) {
    uint32_t v;
    asm volatile("ld.shared.b32 %0, [%1];" : "=r"(v) : "r"(addr));
    return v;
}
__device__ __forceinline__ void mma8(float c[4], const uint32_t a[4], const uint32_t b[2]) {
    asm volatile(
        "mma.sync.aligned.m16n8k8.row.col.f32.tf32.tf32.f32 "
        "{%0,%1,%2,%3}, {%4,%5,%6,%7}, {%8,%9}, {%0,%1,%2,%3};\n"
        : "+f"(c[0]), "+f"(c[1]), "+f"(c[2]), "+f"(c[3])
        : "r"(a[0]), "r"(a[1]), "r"(a[2]), "r"(a[3]), "r"(b[0]), "r"(b[1]));
}

__device__ __forceinline__ float block_sum(float v) {
    #pragma unroll
    for (int o = 16; o; o >>= 1) v += __shfl_xor_sync(0xffffffffu, v, o);
    __shared__ float sh[32];
    const int w = threadIdx.x >> 5;
    if ((threadIdx.x & 31) == 0) sh[w] = v;
    __syncthreads();
    const int nw = (blockDim.x + 31) >> 5;
    v = (threadIdx.x < (unsigned)nw) ? sh[threadIdx.x] : 0.f;
    if (threadIdx.x < 32) {
        #pragma unroll
        for (int o = 16; o; o >>= 1) v += __shfl_xor_sync(0xffffffffu, v, o);
    }
    __syncthreads();
    return v;
}

// ---------------------------------------------------------------------------
// prep: elementwise tf32 rounding (x and weights)
// ---------------------------------------------------------------------------
__global__ void round4_kernel(const float* __restrict__ s, float* __restrict__ d, int n4) {
    int i = blockIdx.x * blockDim.x + threadIdx.x;
    if (i < n4) {
        float4 v = ((const float4*)s)[i];
        v.x = rna_f(v.x); v.y = rna_f(v.y); v.z = rna_f(v.z); v.w = rna_f(v.w);
        ((float4*)d)[i] = v;
    }
}

// ---------------------------------------------------------------------------
// Loss kernels (unchanged, passing)
// ---------------------------------------------------------------------------
__global__ void loss_partial_kernel(const float* __restrict__ dm,
                                    const float* __restrict__ alpha,
                                    const float* __restrict__ sl,
                                    const float* __restrict__ cptr) {
    const int j = blockIdx.x;
    const size_t base = (size_t)j * KK;
    const float c = cptr[0];
    float s = 0.f;
    for (int k = threadIdx.x; k < KK; k += blockDim.x) {
        float m = fmaf(alpha[k], sl[base + k] - dm[base + k], 1.0f);
        s += fmaxf(m, 0.f) - c;
    }
    float tot = block_sum(s);
    if (threadIdx.x == 0) g_partial[j] = tot;
}
__global__ void loss_final_kernel(float* __restrict__ lossp) {
    float s = 0.f;
    for (int i = threadIdx.x; i < DD; i += blockDim.x) s += g_partial[i];
    float tot = block_sum(s);
    if (threadIdx.x == 0) lossp[0] = tot;
}

// ---------------------------------------------------------------------------
// GEMM: C[M,N] = rna(relu(A[M,K] @ W[K,N] + bias))
// Block 128x256x32, 256 threads (8 warps as 2Mx4N), warp tile 64x64.
// tf32 mma.sync m16n8k8, fp32 accum. 3-stage cp.async pipeline.
// A smem: 128 rows x 128B, XOR-swizzled 16B chunks (chunk ^= row&7).
// B smem: 32 rows x 1040B (256 floats + 16B pad).
// Inputs must already hold tf32-rounded bits (prep kernels / epilogue).
// ---------------------------------------------------------------------------
#define BM 128
#define BN 256
#define BK 32
#define ASTG 16384            // 128 * 128B
#define BSTG 33280            // 32 * 1040B
#define STG_STRIDE (ASTG + BSTG)
#define SMEM_DYN (3 * STG_STRIDE)

__global__ __launch_bounds__(256, 1)
void gemm_mma(const float* __restrict__ A, const float* __restrict__ W,
              const float* __restrict__ bias, float* __restrict__ C,
              int lda, int N, int ktiles) {
    extern __shared__ char dsm[];
    const uint32_t smb = smem_u32(dsm);

    const int tid = threadIdx.x, lane = tid & 31, wid = tid >> 5;
    const int wm = wid & 1, wn = wid >> 1;      // 2 warps along M, 4 along N
    const int gID = lane >> 2, tig = lane & 3;
    const int bm = blockIdx.y, bn = blockIdx.x;

    const float* Abase = A + (size_t)bm * BM * lda;
    const float* Wbase = W + (size_t)bn * BN;

    // ---- stage fill (cp.async, 12 x 16B per thread) ----
    auto issue_stage = [&](int kt, int s) {
        const float* Ag = Abase + kt * BK;
        const float* Wg = Wbase + (size_t)kt * BK * N;
        const uint32_t sa = smb + s * STG_STRIDE;
        const uint32_t sb = sa + ASTG;
        #pragma unroll
        for (int i = 0; i < 4; ++i) {           // A: 1024 chunks / 256 thr
            const int ci = tid + 256 * i;
            const int r = ci >> 3, cc = ci & 7;
            cp_async16(sa + r * 128 + ((cc ^ (r & 7)) << 4),
                       Ag + (size_t)r * lda + cc * 4);
        }
        #pragma unroll
        for (int i = 0; i < 8; ++i) {           // B: 2048 chunks / 256 thr
            const int ci = tid + 256 * i;
            const int r = ci >> 6, cc = ci & 63;
            cp_async16(sb + r * 1040 + (cc << 4),
                       Wg + (size_t)r * N + cc * 4);
        }
        asm volatile("cp.async.commit_group;" ::: "memory");
    };

    issue_stage(0, 0);
    issue_stage(1, 1);

    float acc[4][8][4];
    #pragma unroll
    for (int mt = 0; mt < 4; ++mt)
        #pragma unroll
        for (int nt = 0; nt < 8; ++nt)
            #pragma unroll
            for (int r = 0; r < 4; ++r) acc[mt][nt][r] = 0.f;

    #pragma unroll 1
    for (int kt = 0; kt < ktiles; ++kt) {
        const int s = kt % 3;
        asm volatile("cp.async.wait_group 1;" ::: "memory");
        __syncthreads();
        if (kt + 2 < ktiles) issue_stage(kt + 2, (kt + 2) % 3);
        else asm volatile("cp.async.commit_group;" ::: "memory");  // keep invariant

        const uint32_t sa = smb + s * STG_STRIDE;
        const uint32_t sb = sa + ASTG;

        #pragma unroll
        for (int kk = 0; kk < BK; kk += 8) {
            const int cch = kk >> 2;
            uint32_t a[4][4], b[8][2];
            #pragma unroll
            for (int mt = 0; mt < 4; ++mt) {
                const int r0 = wm * 64 + mt * 16 + gID;
                const int r1 = r0 + 8;
                const uint32_t b0 = sa + r0 * 128 + (tig << 2);
                const uint32_t b1 = sa + r1 * 128 + (tig << 2);
                a[mt][0] = lds32(b0 + ((cch       ^ (r0 & 7)) << 4));
                a[mt][1] = lds32(b1 + ((cch       ^ (r1 & 7)) << 4));
                a[mt][2] = lds32(b0 + (((cch + 1) ^ (r0 & 7)) << 4));
                a[mt][3] = lds32(b1 + (((cch + 1) ^ (r1 & 7)) << 4));
            }
            #pragma unroll
            for (int nt = 0; nt < 8; ++nt) {
                const int n = wn * 64 + nt * 8 + gID;
                const uint32_t adr = sb + (kk + tig) * 1040 + (n << 2);
                b[nt][0] = lds32(adr);
                b[nt][1] = lds32(adr + 4 * 1040);
            }
            #pragma unroll
            for (int mt = 0; mt < 4; ++mt)
                #pragma unroll
                for (int nt = 0; nt < 8; ++nt)
                    mma8(acc[mt][nt], a[mt], b[nt]);
        }
    }

    // Epilogue: bias + relu + tf32-round, float2 stores
    #pragma unroll
    for (int mt = 0; mt < 4; ++mt) {
        const int m0 = bm * BM + wm * 64 + mt * 16 + gID;
        #pragma unroll
        for (int nt = 0; nt < 8; ++nt) {
            const int n = bn * BN + wn * 64 + nt * 8 + tig * 2;
            const float bx = bias[n], by = bias[n + 1];
            float2 v0, v1;
            v0.x = rna_f(fmaxf(acc[mt][nt][0] + bx, 0.f));
            v0.y = rna_f(fmaxf(acc[mt][nt][1] + by, 0.f));
            v1.x = rna_f(fmaxf(acc[mt][nt][2] + bx, 0.f));
            v1.y = rna_f(fmaxf(acc[mt][nt][3] + by, 0.f));
            *(float2*)&C[(size_t)m0 * N + n]       = v0;
            *(float2*)&C[(size_t)(m0 + 8) * N + n] = v1;
        }
    }
}

// ---------------------------------------------------------------------------
// Final layer: probs = sigmoid(h3 @ W4 + b4) (unchanged, passing)
// ---------------------------------------------------------------------------
__global__ void layer4_kernel(const float* __restrict__ h, const float* __restrict__ w4,
                              const float* __restrict__ b4, float* __restrict__ probs) {
    const int row = blockIdx.x;
    const float* hr = h + (size_t)row * HH;
    float s0 = 0.f, s1 = 0.f;
    for (int k = threadIdx.x; k < HH; k += blockDim.x) {
        const float v = hr[k];
        const float2 w = *(const float2*)(w4 + 2 * k);
        s0 = fmaf(v, w.x, s0);
        s1 = fmaf(v, w.y, s1);
    }
    #pragma unroll
    for (int o = 16; o; o >>= 1) {
        s0 += __shfl_xor_sync(0xffffffffu, s0, o);
        s1 += __shfl_xor_sync(0xffffffffu, s1, o);
    }
    __shared__ float sh0[8], sh1[8];
    const int w = threadIdx.x >> 5;
    if ((threadIdx.x & 31) == 0) { sh0[w] = s0; sh1[w] = s1; }
    __syncthreads();
    if (threadIdx.x == 0) {
        float t0 = 0.f, t1 = 0.f;
        #pragma unroll
        for (int i = 0; i < 8; ++i) { t0 += sh0[i]; t1 += sh1[i]; }
        t0 += b4[0]; t1 += b4[1];
        probs[2 * row]     = 1.f / (1.f + expf(-t0));
        probs[2 * row + 1] = 1.f / (1.f + expf(-t1));
    }
}

// ---------------------------------------------------------------------------
// Launch
// ---------------------------------------------------------------------------
extern "C" void kernel_launch(void* const* d_in, const int* in_sizes, int n_in,
                              void* d_out, int out_size) {
    const int s = (n_in >= 15) ? 0 : -2;
    const float* x     = (const float*)d_in[0];
    const float* dm    = (const float*)d_in[1];
    const float* alpha = (const float*)d_in[2];
    const float* sl    = (const float*)d_in[3];
    const float* cst   = (const float*)d_in[4];
    const float* W1 = (const float*)d_in[7 + s];
    const float* b1 = (const float*)d_in[8 + s];
    const float* W2 = (const float*)d_in[9 + s];
    const float* b2 = (const float*)d_in[10 + s];
    const float* W3 = (const float*)d_in[11 + s];
    const float* b3 = (const float*)d_in[12 + s];
    const float* W4 = (const float*)d_in[13 + s];
    const float* b4 = (const float*)d_in[14 + s];

    float* out = (float*)d_out;
    float* probs = out + (out_size - 2 * BSZ);
    float* lossp = (out_size > 2 * BSZ) ? out : nullptr;

    float *buf0, *buf1, *xr, *w1r, *w2r, *w3r;
    cudaGetSymbolAddress((void**)&buf0, g_buf0);
    cudaGetSymbolAddress((void**)&buf1, g_buf1);
    cudaGetSymbolAddress((void**)&xr,   g_xr);
    cudaGetSymbolAddress((void**)&w1r,  g_w1r);
    cudaGetSymbolAddress((void**)&w2r,  g_w2r);
    cudaGetSymbolAddress((void**)&w3r,  g_w3r);

    // prep: tf32-round x and weights (elementwise; layouts unchanged)
    {
        int n4;
        n4 = BSZ * FF / 4; round4_kernel<<<(n4 + 255) / 256, 256>>>(x,  xr,  n4);
        n4 = FF  * HH / 4; round4_kernel<<<(n4 + 255) / 256, 256>>>(W1, w1r, n4);
        n4 = HH  * HH / 4; round4_kernel<<<(n4 + 255) / 256, 256>>>(W2, w2r, n4);
        n4 = HH  * HH / 4; round4_kernel<<<(n4 + 255) / 256, 256>>>(W3, w3r, n4);
    }

    // loss (deterministic two-pass)
    loss_partial_kernel<<<DD, 256>>>(dm, alpha, sl, cst);
    if (lossp) loss_final_kernel<<<1, 1024>>>(lossp);

    cudaFuncSetAttribute(gemm_mma, cudaFuncAttributeMaxDynamicSharedMemorySize, SMEM_DYN);

    dim3 grid(HH / BN, BSZ / BM);  // (16, 128)
    gemm_mma<<<grid, 256, SMEM_DYN>>>(xr,   w1r, b1, buf0, FF, HH, FF / BK);
    gemm_mma<<<grid, 256, SMEM_DYN>>>(buf0, w2r, b2, buf1, HH, HH, HH / BK);
    gemm_mma<<<grid, 256, SMEM_DYN>>>(buf1, w3r, b3, buf0, HH, HH, HH / BK);

    layer4_kernel<<<BSZ, 256>>>(buf0, W4, b4, probs);
}